// round 13
// baseline (speedup 1.0000x reference)
#include <cuda_runtime.h>
#include <cuda_fp16.h>
#include <math_constants.h>

#define HH 512
#define WW 512
#define BB 16
// window p=35, pad=17
// loss = mean(erosion_35x35(min_c x)) - 1   (erosion = separable min filter)

// Intermediate: vertically eroded field, [B][H][W/2], half2 packs (w, w+1)
__device__ __align__(16) __half2 g_t2[BB * HH * WW / 2];
// Per-block partial sums from kernel 2 (1024 blocks)
__device__ float g_partial[1024];

// ---------------------------------------------------------------------------
// Kernel 1: channel-min of x (fp32 -> fp16) fused with vertical min-filter,
// van Herk chunk 35, half2 packed along W.
// Block = 256 thr (8 warps); loader SOFTWARE-PIPELINED (depth-1 prefetch ->
// 6 LDG.128 in flight/thread) with uniform 11-iteration trip count and
// STS.64 stores. Chains on warps ty<4. grid = (W/64, B, 4).
// ---------------------------------------------------------------------------
__global__ __launch_bounds__(256) void k1_vert(const float* __restrict__ x) {
    __shared__ __half2 sm[174 * 32];

    const int tx  = threadIdx.x;
    const int ty  = threadIdx.y;              // 0..7
    const int tid = ty * 32 + tx;
    const int wc0 = blockIdx.x * 64;
    const int b   = blockIdx.y;
    const int z   = blockIdx.z;
    const int r0  = z * 140;                 // 4 chunks * 35 rows per z-group
    const float INF = CUDART_INF_F;

    // ---- Pipelined tile load: rows [r0-17, r0+157), 174 x 16 float4 slots.
    const float* xb = x + (size_t)b * 3 * HH * WW;

    float4 ca, cb, cc;                        // current triple
    bool cv;                                  // current row valid
    int cj = tid;
    {
        int r = cj >> 4, c4 = cj & 15, gh = r0 - 17 + r;
        cv = ((unsigned)gh < HH);             // cj = tid < 2784 always
        if (cv) {
            const float4* p = (const float4*)(xb + (size_t)gh * WW + wc0 + c4 * 4);
            ca = p[0]; cb = p[(HH * WW) / 4]; cc = p[(2 * HH * WW) / 4];
        }
    }
    #pragma unroll
    for (int i = 0; i < 11; i++) {
        // Prefetch next iteration's triple BEFORE consuming the current one
        int nj = cj + 256;
        float4 na, nb, nc;
        bool nv = false;
        if (i < 10 && nj < 2784) {
            int r = nj >> 4, c4 = nj & 15, gh = r0 - 17 + r;
            nv = ((unsigned)gh < HH);
            if (nv) {
                const float4* p = (const float4*)(xb + (size_t)gh * WW + wc0 + c4 * 4);
                na = p[0]; nb = p[(HH * WW) / 4]; nc = p[(2 * HH * WW) / 4];
            }
        }
        // Consume current
        if (cj < 2784) {
            float4 m;
            if (cv) {
                m.x = fminf(ca.x, fminf(cb.x, cc.x));
                m.y = fminf(ca.y, fminf(cb.y, cc.y));
                m.z = fminf(ca.z, fminf(cb.z, cc.z));
                m.w = fminf(ca.w, fminf(cb.w, cc.w));
            } else {
                m = make_float4(INF, INF, INF, INF);
            }
            int r = cj >> 4, c4 = cj & 15;
            __half2 h0 = __floats2half2_rn(m.x, m.y);
            __half2 h1 = __floats2half2_rn(m.z, m.w);
            uint2 pk = make_uint2(*(unsigned*)&h0, *(unsigned*)&h1);
            *(uint2*)&sm[r * 32 + c4 * 2] = pk;   // one STS.64, conflict-free
        }
        cj = nj; ca = na; cb = nb; cc = nc; cv = nv;
    }
    __syncthreads();

    // Chains: warps ty<4 only (chunk = z*4+ty); loader warps retire here.
    if (ty >= 4) return;
    const int c    = z * 4 + ty;
    const int base = 35 * c;
    if (base >= HH) return;
    const int lb = 35 * ty + 17;
    const __half2 HINF = __float2half2_rn(CUDART_INF_F);

    __half2 S[35];
    __half2 run = HINF;
    #pragma unroll
    for (int k = 0; k < 52; k++) {
        if (k == 35) run = HINF;
        run = __hmin2(run, sm[(lb + 34 - k) * 32 + tx]);
        if (k >= 17) S[51 - k] = run;
    }

    run = HINF;
    const size_t ob = (size_t)b * HH;
    const int wcol = (wc0 >> 1) + tx;
    #pragma unroll
    for (int k = 0; k < 52; k++) {
        if (k == 35) run = HINF;
        run = __hmin2(run, sm[(lb + k) * 32 + tx]);
        if (k >= 17) {
            int i = base + k - 17;
            if (i < HH)
                g_t2[(ob + i) * (WW / 2) + wcol] = __hmin2(S[k - 17], run);
        }
    }
}

// ---------------------------------------------------------------------------
// Kernel 2: horizontal min-filter in PAIR DOMAIN, chunk length 36 (verified
// round-9 math), register-resident chains: 18 independent predicated LDG.64
// per thread, then pure register suffix/prefix/combine.
// Thread (tx = chunk slot 0..15, ty = row 0..7); grid = (H/8, B).
// ---------------------------------------------------------------------------
__global__ __launch_bounds__(128) void k2_horiz() {
    __shared__ float red[128];

    const int tx  = threadIdx.x;              // chunk slot 0..15 (t = tx-1)
    const int ty  = threadIdx.y;              // row-in-tile 0..7
    const int tid = ty * 16 + tx;
    const int h0  = blockIdx.x * 8;
    const int b   = blockIdx.y;
    const __half2 HINF2 = __float2half2_rn(CUDART_INF_F);
    const unsigned INFU = 0x7C007C00u;

    const int t = tx - 1;                     // -1..14
    const __half2* rowp = g_t2 + (size_t)(b * HH + h0 + ty) * (WW / 2);

    // Load chunk t (pairs [18t, 18t+18)) and chunk t+1 into registers.
    __half2 ct[18], dt[18];
    #pragma unroll
    for (int j = 0; j < 9; j++) {
        int p0 = 18 * t + 2 * j;
        uint2 v = make_uint2(INFU, INFU);
        if ((unsigned)p0 < 256u) v = *(const uint2*)(rowp + p0);
        ct[2 * j]     = *(__half2*)&v.x;
        ct[2 * j + 1] = *(__half2*)&v.y;
    }
    #pragma unroll
    for (int j = 0; j < 9; j++) {
        int p0 = 18 * (t + 1) + 2 * j;
        uint2 v = make_uint2(INFU, INFU);
        if ((unsigned)p0 < 256u) v = *(const uint2*)(rowp + p0);
        dt[2 * j]     = *(__half2*)&v.x;
        dt[2 * j + 1] = *(__half2*)&v.y;
    }

    // Backward: suffix pair-minima over chunk t
    __half2 SR[18];
    {
        __half2 run = HINF2;
        #pragma unroll
        for (int u = 17; u >= 0; u--) {
            run = __hmin2(run, ct[u]);
            SR[u] = run;
        }
    }

    // Forward over chunk t+1 + parity combine + accumulate
    __half2 hacc = __float2half2_rn(0.0f);
    __half2 Rp  = HINF2;                      // R[n-1]
    __half2 HPp = HINF2;                      // hmin(R[n-1]) broadcast
    const int obase = 36 * t + 18;
    #pragma unroll
    for (int n = 0; n < 18; n++) {
        __half2 v  = dt[n];
        __half2 Rc = __hmin2(Rp, v);          // R[n]
        __half2 srn = (n < 17) ? SR[n + 1] : HINF2;
        unsigned srnu = *(unsigned*)&srn;
        unsigned swp  = __byte_perm(srnu, srnu, 0x1032);
        __half2 hs = __hmin2(srn, *(__half2*)&swp);   // H_S[n+1] broadcast
        unsigned sru = *(unsigned*)&SR[n];
        unsigned Rcu = *(unsigned*)&Rc;
        unsigned Rpu = *(unsigned*)&Rp;
        unsigned HPu = *(unsigned*)&HPp;
        unsigned Au = __byte_perm(sru, Rcu, 0x5432);  // (SR[n].hi, Rc.lo)
        unsigned Bu = __byte_perm(HPu, Rpu, 0x7610);  // (HPp,      Rp.hi)
        __half2 o = __hmin2(__hmin2(*(__half2*)&Au, *(__half2*)&Bu), hs);
        if ((unsigned)(obase + 2 * n) < 512u)
            hacc = __hadd2(hacc, o);
        unsigned rs = __byte_perm(Rcu, Rcu, 0x1032);
        HPp = __hmin2(Rc, *(__half2*)&rs);    // hmin(R[n]) broadcast
        Rp = Rc;
    }
    float2 e2 = __half22float2(hacc);
    float acc = e2.x + e2.y;

    // Deterministic in-block reduction -> one partial per block
    red[tid] = acc;
    __syncthreads();
    #pragma unroll
    for (int s = 64; s > 0; s >>= 1) {
        if (tid < s) red[tid] += red[tid + s];
        __syncthreads();
    }
    if (tid == 0) g_partial[b * 64 + blockIdx.x] = red[0];
}

// ---------------------------------------------------------------------------
// Kernel 3: final reduction of 1024 partials; loss = mean(erosion) - 1.
// ---------------------------------------------------------------------------
__global__ void k3_final(float* __restrict__ out) {
    __shared__ float red[512];
    int tid = threadIdx.x;
    red[tid] = g_partial[tid] + g_partial[tid + 512];
    __syncthreads();
    #pragma unroll
    for (int s = 256; s > 0; s >>= 1) {
        if (tid < s) red[tid] += red[tid + s];
        __syncthreads();
    }
    if (tid == 0) out[0] = red[0] * (1.0f / 4194304.0f) - 1.0f;
}

extern "C" void kernel_launch(void* const* d_in, const int* in_sizes, int n_in,
                              void* d_out, int out_size) {
    const float* x = (const float*)d_in[0];
    float* out = (float*)d_out;

    k1_vert<<<dim3(WW / 64, BB, 4), dim3(32, 8)>>>(x);
    k2_horiz<<<dim3(HH / 8, BB), dim3(16, 8)>>>();
    k3_final<<<1, 512>>>(out);
}